// round 1
// baseline (speedup 1.0000x reference)
#include <cuda_runtime.h>
#include <cstdint>

#define N_NODES 50000
#define N_EDGES 800000
#define F_IN    128
#define HID     64
#define HEADS   4
#define L1_OUT  (HEADS*HID)   // 256
#define CLASSES 40
#define NEG_SLOPE 0.2f
#define EPS 1e-16f

// ---------------- scratch (static device allocations; allowed) --------------
__device__ __align__(16) float g_h1  [(size_t)N_NODES * L1_OUT];   // x@W1
__device__ __align__(16) float g_out1[(size_t)N_NODES * L1_OUT];   // relu(layer1)
__device__ __align__(16) float g_h2  [(size_t)N_NODES * CLASSES];  // out1@W2
__device__ __align__(16) float g_as1[N_NODES * HEADS];
__device__ __align__(16) float g_ad1[N_NODES * HEADS];
__device__ float g_as2[N_NODES];
__device__ float g_ad2[N_NODES];
__device__ int   g_cnt[N_NODES];
__device__ int   g_start[N_NODES];
__device__ int   g_cursor[N_NODES];
__device__ int   g_ssrc[N_EDGES];
__device__ int   g_idx_is64;

// ---------------- helpers ---------------------------------------------------
__device__ __forceinline__ float warpMax(float v) {
#pragma unroll
    for (int s = 16; s > 0; s >>= 1)
        v = fmaxf(v, __shfl_xor_sync(0xffffffffu, v, s));
    return v;
}
__device__ __forceinline__ float warpSum(float v) {
#pragma unroll
    for (int s = 16; s > 0; s >>= 1)
        v += __shfl_xor_sync(0xffffffffu, v, s);
    return v;
}
__device__ __forceinline__ float lrelu(float x) {
    return (x > 0.f) ? x : NEG_SLOPE * x;
}

// ---------------- sort-by-dst pipeline --------------------------------------
__global__ void zero_cnt_kernel() {
    int i = blockIdx.x * blockDim.x + threadIdx.x;
    if (i < N_NODES) g_cnt[i] = 0;
    if (i == 0) g_idx_is64 = 1;
}

// Detect whether edge_index is stored as int64 or int32. If it's int32, the
// first N_EDGES int64-interpreted words combine two indices and are almost
// surely out of [0, N_NODES).
__global__ void detect_kernel(const long long* __restrict__ ei) {
    int i = blockIdx.x * blockDim.x + threadIdx.x;
    if (i < N_EDGES) {
        long long v = ei[i];
        if (v < 0 || v >= N_NODES) g_idx_is64 = 0;
    }
}

__global__ void hist_kernel(const void* __restrict__ eiv) {
    int e = blockIdx.x * blockDim.x + threadIdx.x;
    if (e >= N_EDGES) return;
    int dst;
    if (g_idx_is64) dst = (int)((const long long*)eiv)[N_EDGES + e];
    else            dst = ((const int*)eiv)[N_EDGES + e];
    atomicAdd(&g_cnt[dst], 1);
}

// single-block exclusive scan of g_cnt -> g_start (and g_cursor copy)
__global__ void scan_kernel() {
    __shared__ int sh[2][1024];
    __shared__ int base_sh;
    if (threadIdx.x == 0) base_sh = 0;
    __syncthreads();
    for (int off = 0; off < N_NODES; off += 1024) {
        int i = off + threadIdx.x;
        int v = (i < N_NODES) ? g_cnt[i] : 0;
        int cur = 0;
        sh[0][threadIdx.x] = v;
        __syncthreads();
#pragma unroll
        for (int s = 1; s < 1024; s <<= 1) {
            int nxt = cur ^ 1;
            int t = sh[cur][threadIdx.x];
            if ((int)threadIdx.x >= s) t += sh[cur][threadIdx.x - s];
            sh[nxt][threadIdx.x] = t;
            cur = nxt;
            __syncthreads();
        }
        int incl = sh[cur][threadIdx.x];
        int base = base_sh;
        if (i < N_NODES) {
            int st = base + incl - v;
            g_start[i]  = st;
            g_cursor[i] = st;
        }
        __syncthreads();
        if (threadIdx.x == 1023) base_sh = base + incl;
        __syncthreads();
    }
}

__global__ void scatter_kernel(const void* __restrict__ eiv) {
    int e = blockIdx.x * blockDim.x + threadIdx.x;
    if (e >= N_EDGES) return;
    int src, dst;
    if (g_idx_is64) {
        src = (int)((const long long*)eiv)[e];
        dst = (int)((const long long*)eiv)[N_EDGES + e];
    } else {
        src = ((const int*)eiv)[e];
        dst = ((const int*)eiv)[N_EDGES + e];
    }
    int pos = atomicAdd(&g_cursor[dst], 1);
    g_ssrc[pos] = src;
}

// ---------------- generic tiled fp32 GEMM -----------------------------------
// C[N,M] = A[N,K] @ B[K,M]; row bounds checked against Nrows.
template <int BM, int BN, int BK, int TM, int TN, int K, int M>
__global__ void sgemm_kernel(const float* __restrict__ A,
                             const float* __restrict__ B,
                             float* __restrict__ C, int Nrows) {
    constexpr int THREADS = (BM / TM) * (BN / TN);
    __shared__ float As[BK][BM];
    __shared__ float Bs[BK][BN];
    int tid = threadIdx.x;
    int tc = tid % (BN / TN);
    int tr = tid / (BN / TN);
    int bm = blockIdx.y * BM, bn = blockIdx.x * BN;
    float acc[TM][TN] = {};
    for (int k0 = 0; k0 < K; k0 += BK) {
#pragma unroll
        for (int i = tid; i < BM * BK; i += THREADS) {
            int c = i % BK, r = i / BK;
            int gr = bm + r;
            As[c][r] = (gr < Nrows) ? A[(size_t)gr * K + k0 + c] : 0.f;
        }
#pragma unroll
        for (int i = tid; i < BK * BN; i += THREADS) {
            int c = i % BN, r = i / BN;
            Bs[r][c] = B[(size_t)(k0 + r) * M + bn + c];
        }
        __syncthreads();
#pragma unroll
        for (int k = 0; k < BK; k++) {
            float a[TM], b[TN];
#pragma unroll
            for (int x = 0; x < TM; x++) a[x] = As[k][tr * TM + x];
#pragma unroll
            for (int y = 0; y < TN; y++) b[y] = Bs[k][tc * TN + y];
#pragma unroll
            for (int x = 0; x < TM; x++)
#pragma unroll
                for (int y = 0; y < TN; y++)
                    acc[x][y] = fmaf(a[x], b[y], acc[x][y]);
        }
        __syncthreads();
    }
#pragma unroll
    for (int x = 0; x < TM; x++) {
        int gr = bm + tr * TM + x;
        if (gr >= Nrows) continue;
#pragma unroll
        for (int y = 0; y < TN; y++)
            C[(size_t)gr * M + bn + tc * TN + y] = acc[x][y];
    }
}

// ---------------- attention coefficients ------------------------------------
// one warp per (node, head); alpha_s/alpha_d = <h1[n,h,:], a_{src,dst}1[h,:]>
__global__ void alpha1_kernel(const float* __restrict__ a_src,
                              const float* __restrict__ a_dst) {
    int gw = (blockIdx.x * blockDim.x + threadIdx.x) >> 5;
    if (gw >= N_NODES * HEADS) return;
    int lane = threadIdx.x & 31;
    int n = gw >> 2, h = gw & 3;
    const float* hp = g_h1 + (size_t)n * L1_OUT + h * HID;
    float v0 = hp[lane], v1 = hp[32 + lane];
    const float* as = a_src + h * HID;
    const float* ad = a_dst + h * HID;
    float ds = v0 * as[lane] + v1 * as[32 + lane];
    float dd = v0 * ad[lane] + v1 * ad[32 + lane];
    ds = warpSum(ds);
    dd = warpSum(dd);
    if (lane == 0) {
        g_as1[n * HEADS + h] = ds;
        g_ad1[n * HEADS + h] = dd;
    }
}

// one warp per node; 40-dim dots against a_src2/a_dst2
__global__ void alpha2_kernel(const float* __restrict__ a_src,
                              const float* __restrict__ a_dst) {
    int n = (blockIdx.x * blockDim.x + threadIdx.x) >> 5;
    if (n >= N_NODES) return;
    int lane = threadIdx.x & 31;
    const float* hp = g_h2 + (size_t)n * CLASSES;
    float v0 = hp[lane];
    float v1 = (lane < 8) ? hp[32 + lane] : 0.f;
    float ds = v0 * a_src[lane] + ((lane < 8) ? v1 * a_src[32 + lane] : 0.f);
    float dd = v0 * a_dst[lane] + ((lane < 8) ? v1 * a_dst[32 + lane] : 0.f);
    ds = warpSum(ds);
    dd = warpSum(dd);
    if (lane == 0) {
        g_as2[n] = ds;
        g_ad2[n] = dd;
    }
}

// ---------------- layer-1 aggregation: warp per destination node ------------
// lane covers 8 consecutive dims of the 256-wide row; head = lane>>3.
__global__ void agg1_kernel(const float* __restrict__ b1) {
    int n = (blockIdx.x * blockDim.x + threadIdx.x) >> 5;
    if (n >= N_NODES) return;
    int lane = threadIdx.x & 31;
    int head = lane >> 3;
    int s0 = g_start[n];
    int c  = g_cnt[n];
    float4 adv = *(const float4*)(g_ad1 + n * 4);

    // pass 1: per-head segment max of leaky_relu(alpha_s[src]+alpha_d[n])
    float m0 = -1e30f, m1 = -1e30f, m2 = -1e30f, m3 = -1e30f;
    for (int i = lane; i < c; i += 32) {
        int s = g_ssrc[s0 + i];
        float4 av = *(const float4*)(g_as1 + s * 4);
        m0 = fmaxf(m0, lrelu(av.x + adv.x));
        m1 = fmaxf(m1, lrelu(av.y + adv.y));
        m2 = fmaxf(m2, lrelu(av.z + adv.z));
        m3 = fmaxf(m3, lrelu(av.w + adv.w));
    }
    m0 = warpMax(m0); m1 = warpMax(m1); m2 = warpMax(m2); m3 = warpMax(m3);
    float maxh = (head == 0) ? m0 : (head == 1) ? m1 : (head == 2) ? m2 : m3;
    float adh  = (head == 0) ? adv.x : (head == 1) ? adv.y : (head == 2) ? adv.z : adv.w;

    // pass 2: denom = sum exp, acc = sum exp*h1[src] (single sweep, fused)
    float a0=0,a1=0,a2=0,a3=0,a4=0,a5=0,a6=0,a7=0, denom=0.f;
    for (int i = 0; i < c; i++) {
        int s = g_ssrc[s0 + i];
        float e = lrelu(g_as1[s * 4 + head] + adh);
        float ex = __expf(e - maxh);
        denom += ex;
        const float4* hp = (const float4*)(g_h1 + (size_t)s * L1_OUT + lane * 8);
        float4 v0 = hp[0], v1 = hp[1];
        a0 = fmaf(ex, v0.x, a0); a1 = fmaf(ex, v0.y, a1);
        a2 = fmaf(ex, v0.z, a2); a3 = fmaf(ex, v0.w, a3);
        a4 = fmaf(ex, v1.x, a4); a5 = fmaf(ex, v1.y, a5);
        a6 = fmaf(ex, v1.z, a6); a7 = fmaf(ex, v1.w, a7);
    }
    float inv = 1.0f / (denom + EPS);
    int col = lane * 8;
    float4 bA = *(const float4*)(b1 + col);
    float4 bB = *(const float4*)(b1 + col + 4);
    float4 oA, oB;
    oA.x = fmaxf(0.f, fmaf(a0, inv, bA.x));
    oA.y = fmaxf(0.f, fmaf(a1, inv, bA.y));
    oA.z = fmaxf(0.f, fmaf(a2, inv, bA.z));
    oA.w = fmaxf(0.f, fmaf(a3, inv, bA.w));
    oB.x = fmaxf(0.f, fmaf(a4, inv, bB.x));
    oB.y = fmaxf(0.f, fmaf(a5, inv, bB.y));
    oB.z = fmaxf(0.f, fmaf(a6, inv, bB.z));
    oB.w = fmaxf(0.f, fmaf(a7, inv, bB.w));
    *(float4*)(g_out1 + (size_t)n * L1_OUT + col)     = oA;
    *(float4*)(g_out1 + (size_t)n * L1_OUT + col + 4) = oB;
}

// ---------------- layer-2 aggregation + fused log_softmax -------------------
__global__ void agg2_kernel(const float* __restrict__ b2,
                            float* __restrict__ out) {
    int n = (blockIdx.x * blockDim.x + threadIdx.x) >> 5;
    if (n >= N_NODES) return;
    int lane = threadIdx.x & 31;
    int s0 = g_start[n];
    int c  = g_cnt[n];
    float adn = g_ad2[n];

    float m = -1e30f;
    for (int i = lane; i < c; i += 32) {
        int s = g_ssrc[s0 + i];
        m = fmaxf(m, lrelu(g_as2[s] + adn));
    }
    m = warpMax(m);

    float acc0 = 0.f, acc1 = 0.f, denom = 0.f;
    for (int i = 0; i < c; i++) {
        int s = g_ssrc[s0 + i];
        float e = lrelu(g_as2[s] + adn);
        float ex = __expf(e - m);
        denom += ex;
        const float* hp = g_h2 + (size_t)s * CLASSES;
        acc0 = fmaf(ex, hp[lane], acc0);
        if (lane < 8) acc1 = fmaf(ex, hp[32 + lane], acc1);
    }
    float inv = 1.0f / (denom + EPS);
    float o0 = fmaf(acc0, inv, b2[lane]);
    float o1 = (lane < 8) ? fmaf(acc1, inv, b2[32 + lane]) : -1e30f;

    // log_softmax over the 40 values spread across the warp
    float mx = warpMax(fmaxf(o0, o1));
    float se = __expf(o0 - mx) + ((lane < 8) ? __expf(o1 - mx) : 0.f);
    se = warpSum(se);
    float ls = __logf(se);
    out[(size_t)n * CLASSES + lane] = o0 - mx - ls;
    if (lane < 8) out[(size_t)n * CLASSES + 32 + lane] = o1 - mx - ls;
}

// ---------------- launch -----------------------------------------------------
extern "C" void kernel_launch(void* const* d_in, const int* in_sizes, int n_in,
                              void* d_out, int out_size) {
    const float* x    = (const float*)d_in[0];
    const void*  ei   = d_in[1];
    const float* W1   = (const float*)d_in[2];
    const float* asr1 = (const float*)d_in[3];
    const float* adt1 = (const float*)d_in[4];
    const float* b1   = (const float*)d_in[5];
    const float* W2   = (const float*)d_in[6];
    const float* asr2 = (const float*)d_in[7];
    const float* adt2 = (const float*)d_in[8];
    const float* b2   = (const float*)d_in[9];
    float* out = (float*)d_out;

    void *p_h1, *p_out1, *p_h2;
    cudaGetSymbolAddress(&p_h1, g_h1);
    cudaGetSymbolAddress(&p_out1, g_out1);
    cudaGetSymbolAddress(&p_h2, g_h2);

    // GEMM1: h1 = x @ W1   [50000,128]x[128,256]
    sgemm_kernel<64, 64, 16, 4, 4, F_IN, L1_OUT>
        <<<dim3(L1_OUT / 64, (N_NODES + 63) / 64), 256>>>(x, W1, (float*)p_h1, N_NODES);

    // edge sort-by-dst pipeline
    zero_cnt_kernel<<<(N_NODES + 255) / 256, 256>>>();
    detect_kernel<<<(N_EDGES + 255) / 256, 256>>>((const long long*)ei);
    hist_kernel<<<(N_EDGES + 255) / 256, 256>>>(ei);
    scan_kernel<<<1, 1024>>>();
    scatter_kernel<<<(N_EDGES + 255) / 256, 256>>>(ei);

    // layer-1 attention scores + aggregation
    alpha1_kernel<<<(N_NODES * HEADS) / 8, 256>>>(asr1, adt1);
    agg1_kernel<<<N_NODES / 8, 256>>>(b1);

    // GEMM2: h2 = out1 @ W2   [50000,256]x[256,40]
    sgemm_kernel<64, 40, 32, 4, 5, L1_OUT, CLASSES>
        <<<dim3(1, (N_NODES + 63) / 64), 128>>>((const float*)p_out1, W2, (float*)p_h2, N_NODES);

    // layer-2 attention + aggregation + log_softmax
    alpha2_kernel<<<N_NODES / 8, 256>>>(asr2, adt2);
    agg2_kernel<<<N_NODES / 8, 256>>>(b2, out);
}

// round 2
// speedup vs baseline: 1.7978x; 1.7978x over previous
#include <cuda_runtime.h>
#include <cstdint>

#define N_NODES 50000
#define N_EDGES 800000
#define F_IN    128
#define HID     64
#define HEADS   4
#define L1_OUT  (HEADS*HID)   // 256
#define CLASSES 40
#define NEG_SLOPE 0.2f
#define EPS 1e-16f

// ---------------- scratch --------------------------------------------------
__device__ __align__(16) float g_h1  [(size_t)N_NODES * L1_OUT];
__device__ __align__(16) float g_out1[(size_t)N_NODES * L1_OUT];
__device__ __align__(16) float g_h2  [(size_t)N_NODES * CLASSES];
__device__ __align__(16) float g_as1[N_NODES * HEADS];
__device__ __align__(16) float g_ad1[N_NODES * HEADS];
__device__ float g_as2[N_NODES];
__device__ float g_ad2[N_NODES];
__device__ int   g_cnt[N_NODES];
__device__ int   g_start[N_NODES];
__device__ int   g_cursor[N_NODES];
__device__ int   g_ssrc[N_EDGES];
__device__ int   g_idx_is64;
__device__ int   g_bsum[64];
__device__ int   g_boff[64];

// ---------------- helpers ---------------------------------------------------
__device__ __forceinline__ float warpMax(float v) {
#pragma unroll
    for (int s = 16; s > 0; s >>= 1)
        v = fmaxf(v, __shfl_xor_sync(0xffffffffu, v, s));
    return v;
}
__device__ __forceinline__ float warpSum(float v) {
#pragma unroll
    for (int s = 16; s > 0; s >>= 1)
        v += __shfl_xor_sync(0xffffffffu, v, s);
    return v;
}
__device__ __forceinline__ float lrelu(float x) {
    return (x > 0.f) ? x : NEG_SLOPE * x;
}

// ---------------- sort-by-dst pipeline --------------------------------------
__global__ void zero_init_kernel() {
    int i = blockIdx.x * blockDim.x + threadIdx.x;
    if (i < N_NODES) g_cnt[i] = 0;
    if (i == 0) g_idx_is64 = 1;
}

__global__ void detect_kernel(const long long* __restrict__ ei) {
    int i = blockIdx.x * blockDim.x + threadIdx.x;
    if (i < N_EDGES) {
        long long v = ei[i];
        if (v < 0 || v >= N_NODES) g_idx_is64 = 0;
    }
}

__global__ void hist_kernel(const void* __restrict__ eiv) {
    int e = blockIdx.x * blockDim.x + threadIdx.x;
    if (e >= N_EDGES) return;
    int dst;
    if (g_idx_is64) dst = (int)((const long long*)eiv)[N_EDGES + e];
    else            dst = ((const int*)eiv)[N_EDGES + e];
    atomicAdd(&g_cnt[dst], 1);
}

// two-level scan: per-block Kogge-Stone, block sums, add offsets
__global__ void scan1_kernel() {
    __shared__ int sh[2][1024];
    int i = blockIdx.x * 1024 + threadIdx.x;
    int v = (i < N_NODES) ? g_cnt[i] : 0;
    sh[0][threadIdx.x] = v;
    __syncthreads();
    int cur = 0;
#pragma unroll
    for (int s = 1; s < 1024; s <<= 1) {
        int nxt = cur ^ 1;
        int t = sh[cur][threadIdx.x];
        if ((int)threadIdx.x >= s) t += sh[cur][threadIdx.x - s];
        sh[nxt][threadIdx.x] = t;
        cur = nxt;
        __syncthreads();
    }
    int incl = sh[cur][threadIdx.x];
    if (i < N_NODES) g_start[i] = incl - v;   // exclusive within block
    if (threadIdx.x == 1023) g_bsum[blockIdx.x] = incl;
}

__global__ void scan2_kernel(int nblk) {
    __shared__ int sh[64];
    int t = threadIdx.x;
    int v = (t < nblk) ? g_bsum[t] : 0;
    sh[t] = v;
    __syncthreads();
#pragma unroll
    for (int s = 1; s < 64; s <<= 1) {
        int add = (t >= s) ? sh[t - s] : 0;
        __syncthreads();
        sh[t] += add;
        __syncthreads();
    }
    if (t < nblk) g_boff[t] = sh[t] - v;
}

__global__ void scan3_kernel() {
    int i = blockIdx.x * 1024 + threadIdx.x;
    if (i < N_NODES) {
        int st = g_start[i] + g_boff[blockIdx.x];
        g_start[i]  = st;
        g_cursor[i] = st;
    }
}

__global__ void scatter_kernel(const void* __restrict__ eiv) {
    int e = blockIdx.x * blockDim.x + threadIdx.x;
    if (e >= N_EDGES) return;
    int src, dst;
    if (g_idx_is64) {
        src = (int)((const long long*)eiv)[e];
        dst = (int)((const long long*)eiv)[N_EDGES + e];
    } else {
        src = ((const int*)eiv)[e];
        dst = ((const int*)eiv)[N_EDGES + e];
    }
    int pos = atomicAdd(&g_cursor[dst], 1);
    g_ssrc[pos] = src;
}

// ---------------- GEMM1 fused with alpha1 ------------------------------------
// C = x[50000,128] @ W1[128,256]; also g_as1/g_ad1 = per-(row,head) dots.
// 128x128 tile, BK=16, 256 threads, TM=TN=8.
__global__ __launch_bounds__(256) void gemm1_kernel(
    const float* __restrict__ A, const float* __restrict__ B,
    const float* __restrict__ a_src, const float* __restrict__ a_dst)
{
    __shared__ float As[16][128];
    __shared__ float Bs[16][128];
    int tid = threadIdx.x;
    int tr = tid >> 4, tc = tid & 15;
    int bm = blockIdx.y * 128;
    int bn = blockIdx.x * 128;

    int arow = tid >> 1;
    int acol = (tid & 1) * 8;
    int brow = tid >> 4;
    int bcol = (tid & 15) * 8;

    const float* Aptr = A + (size_t)(bm + arow) * F_IN + acol;
    bool aval = (bm + arow) < N_NODES;
    const float* Bptr = B + (size_t)brow * L1_OUT + bn + bcol;

    float4 ra0, ra1, rb0, rb1;
    float4 z = make_float4(0.f, 0.f, 0.f, 0.f);
    ra0 = aval ? __ldg((const float4*)Aptr)       : z;
    ra1 = aval ? __ldg((const float4*)(Aptr + 4)) : z;
    rb0 = __ldg((const float4*)Bptr);
    rb1 = __ldg((const float4*)(Bptr + 4));

    float acc[8][8] = {};

    for (int kk = 0; kk < F_IN / 16; kk++) {
        __syncthreads();
        As[acol + 0][arow] = ra0.x; As[acol + 1][arow] = ra0.y;
        As[acol + 2][arow] = ra0.z; As[acol + 3][arow] = ra0.w;
        As[acol + 4][arow] = ra1.x; As[acol + 5][arow] = ra1.y;
        As[acol + 6][arow] = ra1.z; As[acol + 7][arow] = ra1.w;
        *(float4*)&Bs[brow][bcol]     = rb0;
        *(float4*)&Bs[brow][bcol + 4] = rb1;
        __syncthreads();
        if (kk < F_IN / 16 - 1) {
            int k0 = (kk + 1) * 16;
            ra0 = aval ? __ldg((const float4*)(Aptr + k0))     : z;
            ra1 = aval ? __ldg((const float4*)(Aptr + k0 + 4)) : z;
            rb0 = __ldg((const float4*)(Bptr + (size_t)k0 * L1_OUT));
            rb1 = __ldg((const float4*)(Bptr + (size_t)k0 * L1_OUT + 4));
        }
#pragma unroll
        for (int k = 0; k < 16; k++) {
            float4 av0 = *(const float4*)&As[k][tr * 8];
            float4 av1 = *(const float4*)&As[k][tr * 8 + 4];
            float4 bv0 = *(const float4*)&Bs[k][tc * 8];
            float4 bv1 = *(const float4*)&Bs[k][tc * 8 + 4];
            float a[8] = {av0.x, av0.y, av0.z, av0.w, av1.x, av1.y, av1.z, av1.w};
            float b[8] = {bv0.x, bv0.y, bv0.z, bv0.w, bv1.x, bv1.y, bv1.z, bv1.w};
#pragma unroll
            for (int x = 0; x < 8; x++)
#pragma unroll
                for (int y = 0; y < 8; y++)
                    acc[x][y] = fmaf(a[x], b[y], acc[x][y]);
        }
    }

    // epilogue: C store + fused alpha dots
    int head = (bn >> 6) + (tc >> 3);           // all 8 cols of this thread share head
    int chbase = (tc & 7) * 8;
    float asv[8], adv[8];
#pragma unroll
    for (int y = 0; y < 8; y++) {
        asv[y] = __ldg(a_src + head * HID + chbase + y);
        adv[y] = __ldg(a_dst + head * HID + chbase + y);
    }
    float ps[8], pd[8];
#pragma unroll
    for (int x = 0; x < 8; x++) {
        float s = 0.f, d = 0.f;
#pragma unroll
        for (int y = 0; y < 8; y++) {
            s = fmaf(acc[x][y], asv[y], s);
            d = fmaf(acc[x][y], adv[y], d);
        }
        ps[x] = s; pd[x] = d;
    }
#pragma unroll
    for (int s = 1; s < 8; s <<= 1) {
#pragma unroll
        for (int x = 0; x < 8; x++) {
            ps[x] += __shfl_xor_sync(0xffffffffu, ps[x], s);
            pd[x] += __shfl_xor_sync(0xffffffffu, pd[x], s);
        }
    }
#pragma unroll
    for (int x = 0; x < 8; x++) {
        int r = bm + tr * 8 + x;
        if (r < N_NODES) {
            float* cp = g_h1 + (size_t)r * L1_OUT + bn + tc * 8;
            float4 o0 = {acc[x][0], acc[x][1], acc[x][2], acc[x][3]};
            float4 o1 = {acc[x][4], acc[x][5], acc[x][6], acc[x][7]};
            *(float4*)cp       = o0;
            *(float4*)(cp + 4) = o1;
            if ((tc & 7) == 0) {
                g_as1[r * 4 + head] = ps[x];
                g_ad1[r * 4 + head] = pd[x];
            }
        }
    }
}

// ---------------- layer-1 aggregation (single sweep, no max pass) -----------
// softmax is shift-invariant; |e| is O(5) so exp without max is safe.
__global__ __launch_bounds__(256) void agg1_kernel(const float* __restrict__ b1) {
    int n = (blockIdx.x * blockDim.x + threadIdx.x) >> 5;
    if (n >= N_NODES) return;
    int lane = threadIdx.x & 31;
    int head = lane >> 3;
    int s0 = g_start[n];
    int c  = g_cnt[n];
    float adh = __ldg(g_ad1 + n * 4 + head);

    float a0=0,a1=0,a2=0,a3=0,a4=0,a5=0,a6=0,a7=0, denom=0.f;
    int i = 0;
    for (; i + 4 <= c; i += 4) {
        int sA = __ldg(g_ssrc + s0 + i);
        int sB = __ldg(g_ssrc + s0 + i + 1);
        int sC = __ldg(g_ssrc + s0 + i + 2);
        int sD = __ldg(g_ssrc + s0 + i + 3);
        float eA = __ldg(g_as1 + sA * 4 + head);
        float eB = __ldg(g_as1 + sB * 4 + head);
        float eC = __ldg(g_as1 + sC * 4 + head);
        float eD = __ldg(g_as1 + sD * 4 + head);
        const float4* pA = (const float4*)(g_h1 + (size_t)sA * L1_OUT + (lane << 3));
        const float4* pB = (const float4*)(g_h1 + (size_t)sB * L1_OUT + (lane << 3));
        const float4* pC = (const float4*)(g_h1 + (size_t)sC * L1_OUT + (lane << 3));
        const float4* pD = (const float4*)(g_h1 + (size_t)sD * L1_OUT + (lane << 3));
        float4 vA0 = __ldg(pA), vA1 = __ldg(pA + 1);
        float4 vB0 = __ldg(pB), vB1 = __ldg(pB + 1);
        float4 vC0 = __ldg(pC), vC1 = __ldg(pC + 1);
        float4 vD0 = __ldg(pD), vD1 = __ldg(pD + 1);
        float xA = __expf(lrelu(eA + adh));
        float xB = __expf(lrelu(eB + adh));
        float xC = __expf(lrelu(eC + adh));
        float xD = __expf(lrelu(eD + adh));
        denom += (xA + xB) + (xC + xD);
        a0 = fmaf(xA, vA0.x, fmaf(xB, vB0.x, fmaf(xC, vC0.x, fmaf(xD, vD0.x, a0))));
        a1 = fmaf(xA, vA0.y, fmaf(xB, vB0.y, fmaf(xC, vC0.y, fmaf(xD, vD0.y, a1))));
        a2 = fmaf(xA, vA0.z, fmaf(xB, vB0.z, fmaf(xC, vC0.z, fmaf(xD, vD0.z, a2))));
        a3 = fmaf(xA, vA0.w, fmaf(xB, vB0.w, fmaf(xC, vC0.w, fmaf(xD, vD0.w, a3))));
        a4 = fmaf(xA, vA1.x, fmaf(xB, vB1.x, fmaf(xC, vC1.x, fmaf(xD, vD1.x, a4))));
        a5 = fmaf(xA, vA1.y, fmaf(xB, vB1.y, fmaf(xC, vC1.y, fmaf(xD, vD1.y, a5))));
        a6 = fmaf(xA, vA1.z, fmaf(xB, vB1.z, fmaf(xC, vC1.z, fmaf(xD, vD1.z, a6))));
        a7 = fmaf(xA, vA1.w, fmaf(xB, vB1.w, fmaf(xC, vC1.w, fmaf(xD, vD1.w, a7))));
    }
    for (; i < c; i++) {
        int s = __ldg(g_ssrc + s0 + i);
        float e = __ldg(g_as1 + s * 4 + head);
        const float4* hp = (const float4*)(g_h1 + (size_t)s * L1_OUT + (lane << 3));
        float4 v0 = __ldg(hp), v1 = __ldg(hp + 1);
        float ex = __expf(lrelu(e + adh));
        denom += ex;
        a0 = fmaf(ex, v0.x, a0); a1 = fmaf(ex, v0.y, a1);
        a2 = fmaf(ex, v0.z, a2); a3 = fmaf(ex, v0.w, a3);
        a4 = fmaf(ex, v1.x, a4); a5 = fmaf(ex, v1.y, a5);
        a6 = fmaf(ex, v1.z, a6); a7 = fmaf(ex, v1.w, a7);
    }
    float inv = 1.0f / (denom + EPS);
    int col = lane * 8;
    float4 bA = *(const float4*)(b1 + col);
    float4 bB = *(const float4*)(b1 + col + 4);
    float4 oA, oB;
    oA.x = fmaxf(0.f, fmaf(a0, inv, bA.x));
    oA.y = fmaxf(0.f, fmaf(a1, inv, bA.y));
    oA.z = fmaxf(0.f, fmaf(a2, inv, bA.z));
    oA.w = fmaxf(0.f, fmaf(a3, inv, bA.w));
    oB.x = fmaxf(0.f, fmaf(a4, inv, bB.x));
    oB.y = fmaxf(0.f, fmaf(a5, inv, bB.y));
    oB.z = fmaxf(0.f, fmaf(a6, inv, bB.z));
    oB.w = fmaxf(0.f, fmaf(a7, inv, bB.w));
    *(float4*)(g_out1 + (size_t)n * L1_OUT + col)     = oA;
    *(float4*)(g_out1 + (size_t)n * L1_OUT + col + 4) = oB;
}

// ---------------- GEMM2 fused with alpha2 ------------------------------------
// g_h2 = g_out1[50000,256] @ W2[256,40]; BM=128, BK=32, 256 thr, TM=4, TN=5.
__global__ __launch_bounds__(256) void gemm2_kernel(
    const float* __restrict__ W2,
    const float* __restrict__ a_src, const float* __restrict__ a_dst)
{
    __shared__ float As[32][128];
    __shared__ float Bs[32][40];
    int tid = threadIdx.x;
    int tr = tid >> 3, tc = tid & 7;       // tr 0..31, tc 0..7
    int bm = blockIdx.x * 128;

    int arow = tid >> 1;
    int acol = (tid & 1) * 16;
    const float* Aptr = g_out1 + (size_t)(bm + arow) * L1_OUT + acol;
    bool aval = (bm + arow) < N_NODES;
    int bidx = tid * 5;                    // 0..1275 (+4 => 1279, exact)

    float4 sa[4];
    float  sb[5];
    float4 z = make_float4(0.f, 0.f, 0.f, 0.f);
#pragma unroll
    for (int q = 0; q < 4; q++)
        sa[q] = aval ? __ldg((const float4*)(Aptr + q * 4)) : z;
#pragma unroll
    for (int j = 0; j < 5; j++) sb[j] = __ldg(W2 + bidx + j);

    float acc[4][5] = {};

    for (int kk = 0; kk < L1_OUT / 32; kk++) {
        __syncthreads();
#pragma unroll
        for (int q = 0; q < 4; q++) {
            As[acol + q * 4 + 0][arow] = sa[q].x;
            As[acol + q * 4 + 1][arow] = sa[q].y;
            As[acol + q * 4 + 2][arow] = sa[q].z;
            As[acol + q * 4 + 3][arow] = sa[q].w;
        }
#pragma unroll
        for (int j = 0; j < 5; j++) ((float*)Bs)[bidx + j] = sb[j];
        __syncthreads();
        if (kk < L1_OUT / 32 - 1) {
            int k0 = (kk + 1) * 32;
#pragma unroll
            for (int q = 0; q < 4; q++)
                sa[q] = aval ? __ldg((const float4*)(Aptr + k0 + q * 4)) : z;
#pragma unroll
            for (int j = 0; j < 5; j++) sb[j] = __ldg(W2 + k0 * CLASSES + bidx + j);
        }
#pragma unroll
        for (int k = 0; k < 32; k++) {
            float4 av = *(const float4*)&As[k][tr * 4];
            float a[4] = {av.x, av.y, av.z, av.w};
            float b[5];
#pragma unroll
            for (int j = 0; j < 5; j++) b[j] = Bs[k][tc * 5 + j];
#pragma unroll
            for (int x = 0; x < 4; x++)
#pragma unroll
                for (int y = 0; y < 5; y++)
                    acc[x][y] = fmaf(a[x], b[y], acc[x][y]);
        }
    }

    // epilogue: C store + fused alpha2 dots (single head)
    float asv[5], adv[5];
#pragma unroll
    for (int y = 0; y < 5; y++) {
        asv[y] = __ldg(a_src + tc * 5 + y);
        adv[y] = __ldg(a_dst + tc * 5 + y);
    }
    float ps[4], pd[4];
#pragma unroll
    for (int x = 0; x < 4; x++) {
        float s = 0.f, d = 0.f;
#pragma unroll
        for (int y = 0; y < 5; y++) {
            s = fmaf(acc[x][y], asv[y], s);
            d = fmaf(acc[x][y], adv[y], d);
        }
        ps[x] = s; pd[x] = d;
    }
#pragma unroll
    for (int s = 1; s < 8; s <<= 1) {
#pragma unroll
        for (int x = 0; x < 4; x++) {
            ps[x] += __shfl_xor_sync(0xffffffffu, ps[x], s);
            pd[x] += __shfl_xor_sync(0xffffffffu, pd[x], s);
        }
    }
#pragma unroll
    for (int x = 0; x < 4; x++) {
        int r = bm + tr * 4 + x;
        if (r < N_NODES) {
            float* cp = g_h2 + (size_t)r * CLASSES + tc * 5;
#pragma unroll
            for (int y = 0; y < 5; y++) cp[y] = acc[x][y];
            if (tc == 0) {
                g_as2[r] = ps[x];
                g_ad2[r] = pd[x];
            }
        }
    }
}

// ---------------- layer-2 aggregation + fused log_softmax -------------------
__global__ __launch_bounds__(256) void agg2_kernel(const float* __restrict__ b2,
                                                   float* __restrict__ out) {
    int n = (blockIdx.x * blockDim.x + threadIdx.x) >> 5;
    if (n >= N_NODES) return;
    int lane = threadIdx.x & 31;
    bool hi = lane < 8;
    int s0 = g_start[n];
    int c  = g_cnt[n];
    float adn = __ldg(g_ad2 + n);

    float acc0 = 0.f, acc1 = 0.f, denom = 0.f;
    int i = 0;
    for (; i + 4 <= c; i += 4) {
        int sA = __ldg(g_ssrc + s0 + i);
        int sB = __ldg(g_ssrc + s0 + i + 1);
        int sC = __ldg(g_ssrc + s0 + i + 2);
        int sD = __ldg(g_ssrc + s0 + i + 3);
        float eA = __ldg(g_as2 + sA), eB = __ldg(g_as2 + sB);
        float eC = __ldg(g_as2 + sC), eD = __ldg(g_as2 + sD);
        float hA0 = __ldg(g_h2 + (size_t)sA * CLASSES + lane);
        float hB0 = __ldg(g_h2 + (size_t)sB * CLASSES + lane);
        float hC0 = __ldg(g_h2 + (size_t)sC * CLASSES + lane);
        float hD0 = __ldg(g_h2 + (size_t)sD * CLASSES + lane);
        float hA1 = hi ? __ldg(g_h2 + (size_t)sA * CLASSES + 32 + lane) : 0.f;
        float hB1 = hi ? __ldg(g_h2 + (size_t)sB * CLASSES + 32 + lane) : 0.f;
        float hC1 = hi ? __ldg(g_h2 + (size_t)sC * CLASSES + 32 + lane) : 0.f;
        float hD1 = hi ? __ldg(g_h2 + (size_t)sD * CLASSES + 32 + lane) : 0.f;
        float xA = __expf(lrelu(eA + adn));
        float xB = __expf(lrelu(eB + adn));
        float xC = __expf(lrelu(eC + adn));
        float xD = __expf(lrelu(eD + adn));
        denom += (xA + xB) + (xC + xD);
        acc0 = fmaf(xA, hA0, fmaf(xB, hB0, fmaf(xC, hC0, fmaf(xD, hD0, acc0))));
        acc1 = fmaf(xA, hA1, fmaf(xB, hB1, fmaf(xC, hC1, fmaf(xD, hD1, acc1))));
    }
    for (; i < c; i++) {
        int s = __ldg(g_ssrc + s0 + i);
        float e = __ldg(g_as2 + s);
        float ex = __expf(lrelu(e + adn));
        denom += ex;
        acc0 = fmaf(ex, __ldg(g_h2 + (size_t)s * CLASSES + lane), acc0);
        if (hi) acc1 = fmaf(ex, __ldg(g_h2 + (size_t)s * CLASSES + 32 + lane), acc1);
    }
    float inv = 1.0f / (denom + EPS);
    float o0 = fmaf(acc0, inv, __ldg(b2 + lane));
    float o1 = hi ? fmaf(acc1, inv, __ldg(b2 + 32 + lane)) : -1e30f;

    float mx = warpMax(fmaxf(o0, o1));
    float se = __expf(o0 - mx) + (hi ? __expf(o1 - mx) : 0.f);
    se = warpSum(se);
    float ls = __logf(se);
    out[(size_t)n * CLASSES + lane] = o0 - mx - ls;
    if (hi) out[(size_t)n * CLASSES + 32 + lane] = o1 - mx - ls;
}

// ---------------- launch -----------------------------------------------------
extern "C" void kernel_launch(void* const* d_in, const int* in_sizes, int n_in,
                              void* d_out, int out_size) {
    const float* x    = (const float*)d_in[0];
    const void*  ei   = d_in[1];
    const float* W1   = (const float*)d_in[2];
    const float* asr1 = (const float*)d_in[3];
    const float* adt1 = (const float*)d_in[4];
    const float* b1   = (const float*)d_in[5];
    const float* W2   = (const float*)d_in[6];
    const float* asr2 = (const float*)d_in[7];
    const float* adt2 = (const float*)d_in[8];
    const float* b2   = (const float*)d_in[9];
    float* out = (float*)d_out;

    const int NSCAN = (N_NODES + 1023) / 1024;   // 49

    zero_init_kernel<<<(N_NODES + 255) / 256, 256>>>();
    detect_kernel<<<(N_EDGES + 255) / 256, 256>>>((const long long*)ei);

    // GEMM1 + alpha1 fused
    gemm1_kernel<<<dim3(L1_OUT / 128, (N_NODES + 127) / 128), 256>>>(x, W1, asr1, adt1);

    // edge sort-by-dst pipeline
    hist_kernel<<<(N_EDGES + 255) / 256, 256>>>(ei);
    scan1_kernel<<<NSCAN, 1024>>>();
    scan2_kernel<<<1, 64>>>(NSCAN);
    scan3_kernel<<<NSCAN, 1024>>>();
    scatter_kernel<<<(N_EDGES + 255) / 256, 256>>>(ei);

    // layer-1 aggregation
    agg1_kernel<<<(N_NODES + 7) / 8, 256>>>(b1);

    // GEMM2 + alpha2 fused
    gemm2_kernel<<<(N_NODES + 127) / 128, 256>>>(W2, asr2, adt2);

    // layer-2 aggregation + log_softmax
    agg2_kernel<<<(N_NODES + 7) / 8, 256>>>(b2, out);
}